// round 10
// baseline (speedup 1.0000x reference)
#include <cuda_runtime.h>
#include <cuda_fp16.h>
#include <math.h>
#include <stdint.h>

#define Bb 2
#define Tt 1024
#define Dd 768
#define Hh 3072
#define Ee 8
#define Nn (Bb*Tt)      // 2048 tokens
#define NK (Nn*2)       // 4096 assignments
#define CAP Nn          // slots per expert

// ---------------- scratch (device globals) ----------------------------------
__device__ __half g_hh[(size_t)Ee * CAP * Hh];   // gelu(x@W1), fp16, slot rows
__device__ float  g_y[(size_t)Ee * CAP * Dd];    // h@W2, slot rows
__device__ __half g_xh[(size_t)Nn * Dd];         // fp16 x
__device__ __half g_w1h[(size_t)Ee * Dd * Hh];
__device__ __half g_w2h[(size_t)Ee * Dd * Hh];
__device__ int   g_counts[Ee];
__device__ float g_topw[NK];
__device__ int   g_slot_tok[Ee * CAP];
__device__ int   g_tok_slot[NK];
__device__ float g_probsum[Ee];

// ---------------- helpers ----------------------------------------------------
__device__ __forceinline__ void cp16(uint32_t dst, const void* src, int pbytes) {
    asm volatile("cp.async.cg.shared.global [%0], [%1], 16, %2;"
                 :: "r"(dst), "l"(src), "r"(pbytes));
}
__device__ __forceinline__ void mma_f16(float c[4], uint32_t a0, uint32_t a1,
                                        uint32_t a2, uint32_t a3,
                                        uint32_t b0, uint32_t b1) {
    asm volatile(
        "mma.sync.aligned.m16n8k16.row.col.f32.f16.f16.f32 "
        "{%0,%1,%2,%3}, {%4,%5,%6,%7}, {%8,%9}, {%0,%1,%2,%3};"
        : "+f"(c[0]), "+f"(c[1]), "+f"(c[2]), "+f"(c[3])
        : "r"(a0), "r"(a1), "r"(a2), "r"(a3), "r"(b0), "r"(b1));
}
__device__ __forceinline__ void ldsm4(uint32_t a[4], uint32_t addr) {
    asm volatile("ldmatrix.sync.aligned.m8n8.x4.shared.b16 {%0,%1,%2,%3}, [%4];"
                 : "=r"(a[0]), "=r"(a[1]), "=r"(a[2]), "=r"(a[3]) : "r"(addr));
}
__device__ __forceinline__ void ldsm4t(uint32_t a[4], uint32_t addr) {
    asm volatile("ldmatrix.sync.aligned.m8n8.x4.trans.shared.b16 {%0,%1,%2,%3}, [%4];"
                 : "=r"(a[0]), "=r"(a[1]), "=r"(a[2]), "=r"(a[3]) : "r"(addr));
}
__device__ __forceinline__ float gelu_exact(float c) {
    return 0.5f * c * (1.f + erff(c * 0.7071067811865475f));
}

// ---------------- setup ------------------------------------------------------
__global__ void init_kernel() {
    int t = threadIdx.x;
    if (t < Ee) { g_counts[t] = 0; g_probsum[t] = 0.f; }
}

__global__ void routing_kernel(const float* __restrict__ x,
                               const float* __restrict__ Wr) {
    int n = blockIdx.x;
    int t = threadIdx.x;
    const float* xr = x + (size_t)n * Dd;
    float a0 = 0.f, a1 = 0.f, a2 = 0.f;
    for (int d = t; d < Dd; d += 128) {
        float xv = xr[d];
        a0 += xv * Wr[d];
        a1 += xv * Wr[Dd + d];
        a2 += xv * Wr[2 * Dd + d];
    }
    __shared__ float s0[128], s1[128], s2[128];
    s0[t] = a0; s1[t] = a1; s2[t] = a2;
    __syncthreads();
    for (int off = 64; off > 0; off >>= 1) {
        if (t < off) { s0[t] += s0[t+off]; s1[t] += s1[t+off]; s2[t] += s2[t+off]; }
        __syncthreads();
    }
    if (t == 0) {
        float z0 = s0[0], z1 = s1[0], z2 = s2[0];
        const float inv3 = 0.57735026918962576f;
        float logits[Ee];
        #pragma unroll
        for (int e = 0; e < Ee; e++) {
            float d0 = (e & 4) ? 1.f : -1.f;
            float d1 = (e & 2) ? 1.f : -1.f;
            float d2 = (e & 1) ? 1.f : -1.f;
            logits[e] = (d0 * z0 + d1 * z1 + d2 * z2) * inv3;
        }
        float m = logits[0];
        #pragma unroll
        for (int e = 1; e < Ee; e++) m = fmaxf(m, logits[e]);
        float p[Ee]; float sum = 0.f;
        #pragma unroll
        for (int e = 0; e < Ee; e++) { p[e] = expf(logits[e] - m); sum += p[e]; }
        float invs = 1.f / sum;
        #pragma unroll
        for (int e = 0; e < Ee; e++) atomicAdd(&g_probsum[e], p[e] * invs);
        int i0 = 0;
        #pragma unroll
        for (int e = 1; e < Ee; e++) if (p[e] > p[i0]) i0 = e;
        int i1 = (i0 == 0) ? 1 : 0;
        #pragma unroll
        for (int e = 0; e < Ee; e++) if (e != i0 && p[e] > p[i1]) i1 = e;
        float v0 = p[i0], v1 = p[i1];
        float wd = 1.f / (v0 + v1);
        g_topw[n*2]   = v0 * wd; g_topw[n*2+1] = v1 * wd;
        int pos0 = atomicAdd(&g_counts[i0], 1);
        int pos1 = atomicAdd(&g_counts[i1], 1);
        int slot0 = i0 * CAP + pos0;
        int slot1 = i1 * CAP + pos1;
        g_slot_tok[slot0] = n;  g_tok_slot[n*2]     = slot0;
        g_slot_tok[slot1] = n;  g_tok_slot[n*2 + 1] = slot1;
    }
}

// one kernel converts W1, W2, x to fp16 (grid-stride over 16B quads)
#define WQ ((Ee*Dd*Hh)/4)
#define XQ ((Nn*Dd)/4)
__global__ void conv_all_kernel(const float* __restrict__ W1,
                                const float* __restrict__ W2,
                                const float* __restrict__ x) {
    __half* w1h = g_w1h;
    __half* w2h = g_w2h;
    __half* xh  = g_xh;
    long long i = blockIdx.x * 256ll + threadIdx.x;
    long long stride = gridDim.x * 256ll;
    long long total = 2ll * WQ + XQ;
    for (; i < total; i += stride) {
        const float* s; __half* d; long long q;
        if (i < WQ)            { s = W1; d = w1h; q = i; }
        else if (i < 2ll * WQ) { s = W2; d = w2h; q = i - WQ; }
        else                   { s = x;  d = xh;  q = i - 2ll * WQ; }
        float4 v = ((const float4*)s)[q];
        __half2* dd = (__half2*)(d + q * 4);
        dd[0] = __floats2half2_rn(v.x, v.y);
        dd[1] = __floats2half2_rn(v.z, v.w);
    }
}

// ---------------- fp16 tensor-core GEMMs ------------------------------------
// Block tile (MI*32) x 128, BK=32. 8 warps 2(m)x4(n), warp tile (MI*16)x32.
// g1: MI=4 (128x128 block). g2: MI=2 (64x128 block, 3 CTAs/SM).
// A smem: TM rows x 64B, swizzle u ^ ((r>>1)&3). B: 32 rows x 256B, u ^ (k&7).
#define BKT 32
#define B_BY (32*256)             // 8 KB per stage
#define NST 4

template<bool G1, int MI, int MINB>
__global__ __launch_bounds__(256, MINB) void moe_gemm(const __half* __restrict__ Wglob) {
    constexpr int TM   = MI * 32;
    constexpr int A_BY = TM * 64;
    constexpr int KTOT = G1 ? Dd : Hh;
    constexpr int NSTR = G1 ? Hh : Dd;
    constexpr int NT   = KTOT / BKT;
    constexpr int ACH  = TM / 64;        // A cp.async iters (g1:2, g2:1)

    int e = blockIdx.z;
    int cnt = g_counts[e];
    int m0 = blockIdx.y * TM;
    if (m0 >= cnt) return;
    int n0 = blockIdx.x * 128;
    int base = e * CAP + m0;
    int rows = min(TM, cnt - m0);

    extern __shared__ char sm[];
    uint32_t uA = (uint32_t)__cvta_generic_to_shared(sm);
    uint32_t uB = uA + NST * A_BY;
    int* stok = (int*)(sm + NST * (A_BY + B_BY));

    int t = threadIdx.x, wid = t >> 5, lane = t & 31;
    int wm0 = (wid & 1) * (MI * 16), wn0 = (wid >> 1) * 32;
    int gid = lane >> 2, tig = lane & 3;

    int la_r = (lane & 7) + ((lane >> 3) & 1) * 8;
    int la_u = (lane >> 4) & 1;
    int lb_k = ((lane >> 3) & 1) * 8 + (lane & 7);
    int lb_n = ((lane >> 4) & 1) * 8;

    const __half* Wb = Wglob + (size_t)e * Dd * Hh;
    const __half* Ag = G1 ? g_xh : g_hh;

    if (G1 && t < TM) stok[t] = (t < rows) ? g_slot_tok[base + t] : -1;
    __syncthreads();

    auto issue = [&](int kt) {
        int buf = kt & (NST - 1);
        uint32_t ab = uA + buf * A_BY;
        uint32_t bb = uB + buf * B_BY;
        #pragma unroll
        for (int i = 0; i < ACH; i++) {               // A: TM*4 x 16B chunks
            int idx = i * 256 + t;
            int r = idx >> 2, u = idx & 3;
            uint32_t dst = ab + r * 64 + ((u ^ ((r >> 1) & 3)) << 4);
            if (G1) {
                int tok = stok[r];
                cp16(dst, Ag + (size_t)max(tok, 0) * KTOT + kt * BKT + u * 8,
                     (tok >= 0) ? 16 : 0);
            } else {
                cp16(dst, Ag + (size_t)(base + min(r, rows - 1)) * KTOT + kt * BKT + u * 8,
                     (r < rows) ? 16 : 0);
            }
        }
        #pragma unroll
        for (int i = 0; i < 2; i++) {                 // B: 512 x 16B chunks
            int idx = i * 256 + t;
            int k = idx >> 4, u = idx & 15;
            uint32_t dst = bb + k * 256 + ((u ^ (k & 7)) << 4);
            cp16(dst, Wb + (size_t)(kt * BKT + k) * NSTR + n0 + u * 8, 16);
        }
        asm volatile("cp.async.commit_group;" ::: "memory");
    };

    issue(0); issue(1); issue(2);

    float acc[MI][4][4] = {};

    for (int j = 0; j < NT; j++) {
        int buf = j & (NST - 1);
        if (j <= NT - 3)      asm volatile("cp.async.wait_group 2;" ::: "memory");
        else if (j == NT - 2) asm volatile("cp.async.wait_group 1;" ::: "memory");
        else                  asm volatile("cp.async.wait_group 0;" ::: "memory");
        __syncthreads();
        if (j + 3 < NT) issue(j + 3);

        uint32_t ab = uA + buf * A_BY;
        uint32_t bb = uB + buf * B_BY;

        #pragma unroll
        for (int ks = 0; ks < 2; ks++) {
            uint32_t a[MI][4];
            #pragma unroll
            for (int mi = 0; mi < MI; mi++) {
                int r = wm0 + mi * 16 + la_r;
                int u = 2 * ks + la_u;
                ldsm4(a[mi], ab + r * 64 + ((u ^ ((r >> 1) & 3)) << 4));
            }
            uint32_t b[2][4];
            #pragma unroll
            for (int half = 0; half < 2; half++) {
                int k = ks * 16 + lb_k;
                int ncol = wn0 + half * 16 + lb_n;
                int u = ncol >> 3;
                ldsm4t(b[half], bb + k * 256 + ((u ^ (k & 7)) << 4));
            }
            #pragma unroll
            for (int mi = 0; mi < MI; mi++)
                #pragma unroll
                for (int ni = 0; ni < 4; ni++)
                    mma_f16(acc[mi][ni], a[mi][0], a[mi][1], a[mi][2], a[mi][3],
                            b[ni >> 1][(ni & 1) * 2], b[ni >> 1][(ni & 1) * 2 + 1]);
        }
    }

    // epilogue
    #pragma unroll
    for (int mi = 0; mi < MI; mi++) {
        int r0 = wm0 + mi * 16 + gid;
        #pragma unroll
        for (int ni = 0; ni < 4; ni++) {
            int c = n0 + wn0 + ni * 8 + tig * 2;
            #pragma unroll
            for (int half = 0; half < 2; half++) {
                int r = r0 + half * 8;
                if (r < rows) {
                    float v0 = acc[mi][ni][half * 2], v1 = acc[mi][ni][half * 2 + 1];
                    if (G1) {
                        *(__half2*)(g_hh + (size_t)(base + r) * Hh + c) =
                            __floats2half2_rn(gelu_exact(v0), gelu_exact(v1));
                    } else {
                        size_t o = (size_t)(base + r) * Dd + c;
                        g_y[o] = v0; g_y[o + 1] = v1;
                    }
                }
            }
        }
    }
}

#define SM1 (NST*(128*64 + B_BY) + 512)   // g1 smem
#define SM2 (NST*(64*64  + B_BY) + 512)   // g2 smem

// ---------------- combine (+fused aux) ---------------------------------------
__global__ void combine_kernel(float* __restrict__ out, int out_size) {
    int idx = blockIdx.x * 256 + threadIdx.x;
    if (idx < Nn * (Dd / 4)) {
        int n = idx / (Dd / 4), q = idx - n * (Dd / 4);
        int s0 = g_tok_slot[n*2], s1 = g_tok_slot[n*2 + 1];
        float w0 = g_topw[n*2], w1 = g_topw[n*2 + 1];
        float4 y0 = *(const float4*)(g_y + (size_t)s0 * Dd + q * 4);
        float4 y1 = *(const float4*)(g_y + (size_t)s1 * Dd + q * 4);
        float4 o;
        o.x = w0 * y0.x + w1 * y1.x;
        o.y = w0 * y0.y + w1 * y1.y;
        o.z = w0 * y0.z + w1 * y1.z;
        o.w = w0 * y0.w + w1 * y1.w;
        *(float4*)(out + (size_t)n * Dd + q * 4) = o;
    }
    if (blockIdx.x == 0 && threadIdx.x == 0) {
        int extra = out_size - Nn * Dd;
        if (extra > 0) {
            float aux = 0.f;
            #pragma unroll
            for (int e = 0; e < Ee; e++) {
                float tpe = g_probsum[e] * (1.0f / (float)Nn);
                float dlt = tpe - 1.0f / (float)Ee;
                aux += dlt * dlt;
            }
            aux = 0.01f * aux / (float)Ee;
            for (int i = 0; i < extra; i++) out[Nn * Dd + i] = aux;
        }
    }
}

// ---------------- launch -----------------------------------------------------
extern "C" void kernel_launch(void* const* d_in, const int* in_sizes, int n_in,
                              void* d_out, int out_size) {
    const float* x  = (const float*)d_in[0];
    const float* Wr = (const float*)d_in[1];
    const float* W1 = (const float*)d_in[2];
    const float* W2 = (const float*)d_in[3];
    float* out = (float*)d_out;

    cudaFuncSetAttribute(moe_gemm<true, 4, 2>,
                         cudaFuncAttributeMaxDynamicSharedMemorySize, SM1);
    cudaFuncSetAttribute(moe_gemm<false, 2, 3>,
                         cudaFuncAttributeMaxDynamicSharedMemorySize, SM2);

    __half* w1h; cudaGetSymbolAddress((void**)&w1h, g_w1h);
    __half* w2h; cudaGetSymbolAddress((void**)&w2h, g_w2h);

    init_kernel<<<1, 32>>>();
    routing_kernel<<<Nn, 128>>>(x, Wr);
    conv_all_kernel<<<4096, 256>>>(W1, W2, x);
    moe_gemm<true, 4, 2><<<dim3(Hh / 128, Nn / 128, Ee), 256, SM1>>>(w1h);
    moe_gemm<false, 2, 3><<<dim3(Dd / 128, Nn / 64, Ee), 256, SM2>>>(w2h);
    combine_kernel<<<(Nn * (Dd / 4) + 255) / 256, 256>>>(out, out_size);
}

// round 11
// speedup vs baseline: 1.2889x; 1.2889x over previous
#include <cuda_runtime.h>
#include <cuda_fp16.h>
#include <math.h>
#include <stdint.h>

#define Bb 2
#define Tt 1024
#define Dd 768
#define Hh 3072
#define Ee 8
#define Nn (Bb*Tt)      // 2048 tokens
#define NK (Nn*2)       // 4096 assignments
#define CAP Nn          // slots per expert

// ---------------- scratch (device globals) ----------------------------------
__device__ __half g_hh[(size_t)Ee * CAP * Hh];   // gelu(x@W1), fp16, slot rows
__device__ float  g_y[(size_t)Ee * CAP * Dd];    // h@W2, slot rows
__device__ __half g_xh[(size_t)Nn * Dd];         // fp16 x
__device__ __half g_w1h[(size_t)Ee * Dd * Hh];
__device__ __half g_w2h[(size_t)Ee * Dd * Hh];
__device__ int   g_counts[Ee];
__device__ float g_topw[NK];
__device__ int   g_slot_tok[Ee * CAP];
__device__ int   g_tok_slot[NK];
__device__ float g_probsum[Ee];

// ---------------- helpers ----------------------------------------------------
__device__ __forceinline__ void cp16(uint32_t dst, const void* src, int pbytes) {
    asm volatile("cp.async.cg.shared.global [%0], [%1], 16, %2;"
                 :: "r"(dst), "l"(src), "r"(pbytes));
}
__device__ __forceinline__ void mma_f16(float c[4], uint32_t a0, uint32_t a1,
                                        uint32_t a2, uint32_t a3,
                                        uint32_t b0, uint32_t b1) {
    asm volatile(
        "mma.sync.aligned.m16n8k16.row.col.f32.f16.f16.f32 "
        "{%0,%1,%2,%3}, {%4,%5,%6,%7}, {%8,%9}, {%0,%1,%2,%3};"
        : "+f"(c[0]), "+f"(c[1]), "+f"(c[2]), "+f"(c[3])
        : "r"(a0), "r"(a1), "r"(a2), "r"(a3), "r"(b0), "r"(b1));
}
__device__ __forceinline__ void ldsm4(uint32_t a[4], uint32_t addr) {
    asm volatile("ldmatrix.sync.aligned.m8n8.x4.shared.b16 {%0,%1,%2,%3}, [%4];"
                 : "=r"(a[0]), "=r"(a[1]), "=r"(a[2]), "=r"(a[3]) : "r"(addr));
}
__device__ __forceinline__ void ldsm4t(uint32_t a[4], uint32_t addr) {
    asm volatile("ldmatrix.sync.aligned.m8n8.x4.trans.shared.b16 {%0,%1,%2,%3}, [%4];"
                 : "=r"(a[0]), "=r"(a[1]), "=r"(a[2]), "=r"(a[3]) : "r"(addr));
}
__device__ __forceinline__ float gelu_exact(float c) {
    return 0.5f * c * (1.f + erff(c * 0.7071067811865475f));
}

// ---------------- setup ------------------------------------------------------
__global__ void init_kernel() {
    int t = threadIdx.x;
    if (t < Ee) { g_counts[t] = 0; g_probsum[t] = 0.f; }
}

__global__ void routing_kernel(const float* __restrict__ x,
                               const float* __restrict__ Wr) {
    int n = blockIdx.x;
    int t = threadIdx.x;
    const float* xr = x + (size_t)n * Dd;
    float a0 = 0.f, a1 = 0.f, a2 = 0.f;
    for (int d = t; d < Dd; d += 128) {
        float xv = xr[d];
        a0 += xv * Wr[d];
        a1 += xv * Wr[Dd + d];
        a2 += xv * Wr[2 * Dd + d];
    }
    __shared__ float s0[128], s1[128], s2[128];
    s0[t] = a0; s1[t] = a1; s2[t] = a2;
    __syncthreads();
    for (int off = 64; off > 0; off >>= 1) {
        if (t < off) { s0[t] += s0[t+off]; s1[t] += s1[t+off]; s2[t] += s2[t+off]; }
        __syncthreads();
    }
    if (t == 0) {
        float z0 = s0[0], z1 = s1[0], z2 = s2[0];
        const float inv3 = 0.57735026918962576f;
        float logits[Ee];
        #pragma unroll
        for (int e = 0; e < Ee; e++) {
            float d0 = (e & 4) ? 1.f : -1.f;
            float d1 = (e & 2) ? 1.f : -1.f;
            float d2 = (e & 1) ? 1.f : -1.f;
            logits[e] = (d0 * z0 + d1 * z1 + d2 * z2) * inv3;
        }
        float m = logits[0];
        #pragma unroll
        for (int e = 1; e < Ee; e++) m = fmaxf(m, logits[e]);
        float p[Ee]; float sum = 0.f;
        #pragma unroll
        for (int e = 0; e < Ee; e++) { p[e] = expf(logits[e] - m); sum += p[e]; }
        float invs = 1.f / sum;
        #pragma unroll
        for (int e = 0; e < Ee; e++) atomicAdd(&g_probsum[e], p[e] * invs);
        int i0 = 0;
        #pragma unroll
        for (int e = 1; e < Ee; e++) if (p[e] > p[i0]) i0 = e;
        int i1 = (i0 == 0) ? 1 : 0;
        #pragma unroll
        for (int e = 0; e < Ee; e++) if (e != i0 && p[e] > p[i1]) i1 = e;
        float v0 = p[i0], v1 = p[i1];
        float wd = 1.f / (v0 + v1);
        g_topw[n*2]   = v0 * wd; g_topw[n*2+1] = v1 * wd;
        int pos0 = atomicAdd(&g_counts[i0], 1);
        int pos1 = atomicAdd(&g_counts[i1], 1);
        int slot0 = i0 * CAP + pos0;
        int slot1 = i1 * CAP + pos1;
        g_slot_tok[slot0] = n;  g_tok_slot[n*2]     = slot0;
        g_slot_tok[slot1] = n;  g_tok_slot[n*2 + 1] = slot1;
    }
}

// one kernel converts W1, W2, x to fp16 (grid-stride over 16B quads)
#define WQ ((Ee*Dd*Hh)/4)
#define XQ ((Nn*Dd)/4)
__global__ void conv_all_kernel(const float* __restrict__ W1,
                                const float* __restrict__ W2,
                                const float* __restrict__ x) {
    __half* w1h = g_w1h;
    __half* w2h = g_w2h;
    __half* xh  = g_xh;
    long long i = blockIdx.x * 256ll + threadIdx.x;
    long long stride = gridDim.x * 256ll;
    long long total = 2ll * WQ + XQ;
    for (; i < total; i += stride) {
        const float* s; __half* d; long long q;
        if (i < WQ)            { s = W1; d = w1h; q = i; }
        else if (i < 2ll * WQ) { s = W2; d = w2h; q = i - WQ; }
        else                   { s = x;  d = xh;  q = i - 2ll * WQ; }
        float4 v = ((const float4*)s)[q];
        __half2* dd = (__half2*)(d + q * 4);
        dd[0] = __floats2half2_rn(v.x, v.y);
        dd[1] = __floats2half2_rn(v.z, v.w);
    }
}

// ---------------- fp16 tensor-core GEMMs ------------------------------------
// Block tile (MI*32) x 128, BK=32. 8 warps 2(m)x4(n), warp tile (MI*16)x32.
// g1: MI=4 (128x128). g2: MI=2 (64x128) for wave balance — MINB stays 2 so
// ptxas keeps <=128 regs (MINB=3 capped at 82 and spilled; round-10 regression).
#define BKT 32
#define B_BY (32*256)             // 8 KB per stage
#define NST 4

template<bool G1, int MI, int MINB>
__global__ __launch_bounds__(256, MINB) void moe_gemm(const __half* __restrict__ Wglob) {
    constexpr int TM   = MI * 32;
    constexpr int A_BY = TM * 64;
    constexpr int KTOT = G1 ? Dd : Hh;
    constexpr int NSTR = G1 ? Hh : Dd;
    constexpr int NT   = KTOT / BKT;
    constexpr int ACH  = TM / 64;        // A cp.async iters (g1:2, g2:1)

    int e = blockIdx.z;
    int cnt = g_counts[e];
    int m0 = blockIdx.y * TM;
    if (m0 >= cnt) return;
    int n0 = blockIdx.x * 128;
    int base = e * CAP + m0;
    int rows = min(TM, cnt - m0);

    extern __shared__ char sm[];
    uint32_t uA = (uint32_t)__cvta_generic_to_shared(sm);
    uint32_t uB = uA + NST * A_BY;
    int* stok = (int*)(sm + NST * (A_BY + B_BY));

    int t = threadIdx.x, wid = t >> 5, lane = t & 31;
    int wm0 = (wid & 1) * (MI * 16), wn0 = (wid >> 1) * 32;
    int gid = lane >> 2, tig = lane & 3;

    int la_r = (lane & 7) + ((lane >> 3) & 1) * 8;
    int la_u = (lane >> 4) & 1;
    int lb_k = ((lane >> 3) & 1) * 8 + (lane & 7);
    int lb_n = ((lane >> 4) & 1) * 8;

    const __half* Wb = Wglob + (size_t)e * Dd * Hh;
    const __half* Ag = G1 ? g_xh : g_hh;

    if (G1 && t < TM) stok[t] = (t < rows) ? g_slot_tok[base + t] : -1;
    __syncthreads();

    auto issue = [&](int kt) {
        int buf = kt & (NST - 1);
        uint32_t ab = uA + buf * A_BY;
        uint32_t bb = uB + buf * B_BY;
        #pragma unroll
        for (int i = 0; i < ACH; i++) {               // A: TM*4 x 16B chunks
            int idx = i * 256 + t;
            int r = idx >> 2, u = idx & 3;
            uint32_t dst = ab + r * 64 + ((u ^ ((r >> 1) & 3)) << 4);
            if (G1) {
                int tok = stok[r];
                cp16(dst, Ag + (size_t)max(tok, 0) * KTOT + kt * BKT + u * 8,
                     (tok >= 0) ? 16 : 0);
            } else {
                cp16(dst, Ag + (size_t)(base + min(r, rows - 1)) * KTOT + kt * BKT + u * 8,
                     (r < rows) ? 16 : 0);
            }
        }
        #pragma unroll
        for (int i = 0; i < 2; i++) {                 // B: 512 x 16B chunks
            int idx = i * 256 + t;
            int k = idx >> 4, u = idx & 15;
            uint32_t dst = bb + k * 256 + ((u ^ (k & 7)) << 4);
            cp16(dst, Wb + (size_t)(kt * BKT + k) * NSTR + n0 + u * 8, 16);
        }
        asm volatile("cp.async.commit_group;" ::: "memory");
    };

    issue(0); issue(1); issue(2);

    float acc[MI][4][4] = {};

    for (int j = 0; j < NT; j++) {
        int buf = j & (NST - 1);
        if (j <= NT - 3)      asm volatile("cp.async.wait_group 2;" ::: "memory");
        else if (j == NT - 2) asm volatile("cp.async.wait_group 1;" ::: "memory");
        else                  asm volatile("cp.async.wait_group 0;" ::: "memory");
        __syncthreads();
        if (j + 3 < NT) issue(j + 3);

        uint32_t ab = uA + buf * A_BY;
        uint32_t bb = uB + buf * B_BY;

        #pragma unroll
        for (int ks = 0; ks < 2; ks++) {
            uint32_t a[MI][4];
            #pragma unroll
            for (int mi = 0; mi < MI; mi++) {
                int r = wm0 + mi * 16 + la_r;
                int u = 2 * ks + la_u;
                ldsm4(a[mi], ab + r * 64 + ((u ^ ((r >> 1) & 3)) << 4));
            }
            uint32_t b[2][4];
            #pragma unroll
            for (int half = 0; half < 2; half++) {
                int k = ks * 16 + lb_k;
                int ncol = wn0 + half * 16 + lb_n;
                int u = ncol >> 3;
                ldsm4t(b[half], bb + k * 256 + ((u ^ (k & 7)) << 4));
            }
            #pragma unroll
            for (int mi = 0; mi < MI; mi++)
                #pragma unroll
                for (int ni = 0; ni < 4; ni++)
                    mma_f16(acc[mi][ni], a[mi][0], a[mi][1], a[mi][2], a[mi][3],
                            b[ni >> 1][(ni & 1) * 2], b[ni >> 1][(ni & 1) * 2 + 1]);
        }
    }

    // epilogue
    #pragma unroll
    for (int mi = 0; mi < MI; mi++) {
        int r0 = wm0 + mi * 16 + gid;
        #pragma unroll
        for (int ni = 0; ni < 4; ni++) {
            int c = n0 + wn0 + ni * 8 + tig * 2;
            #pragma unroll
            for (int half = 0; half < 2; half++) {
                int r = r0 + half * 8;
                if (r < rows) {
                    float v0 = acc[mi][ni][half * 2], v1 = acc[mi][ni][half * 2 + 1];
                    if (G1) {
                        *(__half2*)(g_hh + (size_t)(base + r) * Hh + c) =
                            __floats2half2_rn(gelu_exact(v0), gelu_exact(v1));
                    } else {
                        size_t o = (size_t)(base + r) * Dd + c;
                        g_y[o] = v0; g_y[o + 1] = v1;
                    }
                }
            }
        }
    }
}

#define SM1 (NST*(128*64 + B_BY) + 512)   // g1 smem
#define SM2 (NST*(64*64  + B_BY) + 512)   // g2 smem

// ---------------- combine (+fused aux) ---------------------------------------
__global__ void combine_kernel(float* __restrict__ out, int out_size) {
    int idx = blockIdx.x * 256 + threadIdx.x;
    if (idx < Nn * (Dd / 4)) {
        int n = idx / (Dd / 4), q = idx - n * (Dd / 4);
        int s0 = g_tok_slot[n*2], s1 = g_tok_slot[n*2 + 1];
        float w0 = g_topw[n*2], w1 = g_topw[n*2 + 1];
        float4 y0 = *(const float4*)(g_y + (size_t)s0 * Dd + q * 4);
        float4 y1 = *(const float4*)(g_y + (size_t)s1 * Dd + q * 4);
        float4 o;
        o.x = w0 * y0.x + w1 * y1.x;
        o.y = w0 * y0.y + w1 * y1.y;
        o.z = w0 * y0.z + w1 * y1.z;
        o.w = w0 * y0.w + w1 * y1.w;
        *(float4*)(out + (size_t)n * Dd + q * 4) = o;
    }
    if (blockIdx.x == 0 && threadIdx.x == 0) {
        int extra = out_size - Nn * Dd;
        if (extra > 0) {
            float aux = 0.f;
            #pragma unroll
            for (int e = 0; e < Ee; e++) {
                float tpe = g_probsum[e] * (1.0f / (float)Nn);
                float dlt = tpe - 1.0f / (float)Ee;
                aux += dlt * dlt;
            }
            aux = 0.01f * aux / (float)Ee;
            for (int i = 0; i < extra; i++) out[Nn * Dd + i] = aux;
        }
    }
}

// ---------------- launch -----------------------------------------------------
extern "C" void kernel_launch(void* const* d_in, const int* in_sizes, int n_in,
                              void* d_out, int out_size) {
    const float* x  = (const float*)d_in[0];
    const float* Wr = (const float*)d_in[1];
    const float* W1 = (const float*)d_in[2];
    const float* W2 = (const float*)d_in[3];
    float* out = (float*)d_out;

    cudaFuncSetAttribute(moe_gemm<true, 4, 2>,
                         cudaFuncAttributeMaxDynamicSharedMemorySize, SM1);
    cudaFuncSetAttribute(moe_gemm<false, 2, 2>,
                         cudaFuncAttributeMaxDynamicSharedMemorySize, SM2);

    __half* w1h; cudaGetSymbolAddress((void**)&w1h, g_w1h);
    __half* w2h; cudaGetSymbolAddress((void**)&w2h, g_w2h);

    init_kernel<<<1, 32>>>();
    routing_kernel<<<Nn, 128>>>(x, Wr);
    conv_all_kernel<<<4096, 256>>>(W1, W2, x);
    moe_gemm<true, 4, 2><<<dim3(Hh / 128, Nn / 128, Ee), 256, SM1>>>(w1h);
    moe_gemm<false, 2, 2><<<dim3(Dd / 128, Nn / 64, Ee), 256, SM2>>>(w2h);
    combine_kernel<<<(Nn * (Dd / 4) + 255) / 256, 256>>>(out, out_size);
}

// round 12
// speedup vs baseline: 1.5062x; 1.1686x over previous
#include <cuda_runtime.h>
#include <cuda_fp16.h>
#include <math.h>
#include <stdint.h>

#define Bb 2
#define Tt 1024
#define Dd 768
#define Hh 3072
#define Ee 8
#define Nn (Bb*Tt)      // 2048 tokens
#define NK (Nn*2)       // 4096 assignments
#define CAP Nn          // slots per expert

// ---------------- scratch (device globals) ----------------------------------
__device__ __half g_hh[(size_t)Ee * CAP * Hh];   // gelu(x@W1), fp16, slot rows
__device__ float  g_y[(size_t)Ee * CAP * Dd];    // h@W2, slot rows
__device__ __half g_xh[(size_t)Nn * Dd];         // fp16 x
__device__ __half g_w1h[(size_t)Ee * Dd * Hh];
__device__ __half g_w2h[(size_t)Ee * Dd * Hh];
__device__ int   g_counts[Ee];                   // zero at entry; reset by combine
__device__ float g_topw[NK];
__device__ int   g_slot_tok[Ee * CAP];
__device__ int   g_tok_slot[NK];
__device__ float g_probsum[Ee];                  // zero at entry; reset by combine

// ---------------- helpers ----------------------------------------------------
__device__ __forceinline__ void cp16(uint32_t dst, const void* src, int pbytes) {
    asm volatile("cp.async.cg.shared.global [%0], [%1], 16, %2;"
                 :: "r"(dst), "l"(src), "r"(pbytes));
}
__device__ __forceinline__ void mma_f16(float c[4], uint32_t a0, uint32_t a1,
                                        uint32_t a2, uint32_t a3,
                                        uint32_t b0, uint32_t b1) {
    asm volatile(
        "mma.sync.aligned.m16n8k16.row.col.f32.f16.f16.f32 "
        "{%0,%1,%2,%3}, {%4,%5,%6,%7}, {%8,%9}, {%0,%1,%2,%3};"
        : "+f"(c[0]), "+f"(c[1]), "+f"(c[2]), "+f"(c[3])
        : "r"(a0), "r"(a1), "r"(a2), "r"(a3), "r"(b0), "r"(b1));
}
__device__ __forceinline__ void ldsm4(uint32_t a[4], uint32_t addr) {
    asm volatile("ldmatrix.sync.aligned.m8n8.x4.shared.b16 {%0,%1,%2,%3}, [%4];"
                 : "=r"(a[0]), "=r"(a[1]), "=r"(a[2]), "=r"(a[3]) : "r"(addr));
}
__device__ __forceinline__ void ldsm4t(uint32_t a[4], uint32_t addr) {
    asm volatile("ldmatrix.sync.aligned.m8n8.x4.trans.shared.b16 {%0,%1,%2,%3}, [%4];"
                 : "=r"(a[0]), "=r"(a[1]), "=r"(a[2]), "=r"(a[3]) : "r"(addr));
}
__device__ __forceinline__ float gelu_exact(float c) {
    return 0.5f * c * (1.f + erff(c * 0.7071067811865475f));
}
__device__ __forceinline__ uint32_t pack2(float a, float b) {
    __half2 h = __floats2half2_rn(a, b);
    return *reinterpret_cast<uint32_t*>(&h);
}
// convert one 16B quad (8 fp32 -> 8 fp16)
__device__ __forceinline__ void conv_quad(const float* __restrict__ src,
                                          __half* __restrict__ dst, long long q) {
    const float4* s = reinterpret_cast<const float4*>(src) + q * 2;
    float4 v0 = s[0], v1 = s[1];
    uint4 o;
    o.x = pack2(v0.x, v0.y); o.y = pack2(v0.z, v0.w);
    o.z = pack2(v1.x, v1.y); o.w = pack2(v1.z, v1.w);
    reinterpret_cast<uint4*>(dst)[q] = o;
}

// ---------------- routing (+x fp16, +W1 fp16) --------------------------------
#define W1Q ((long long)(Ee)*Dd*Hh/8)    // 2359296 quads; /2048 blocks = 1152

__global__ void routing_kernel(const float* __restrict__ x,
                               const float* __restrict__ Wr,
                               const float* __restrict__ W1) {
    int n = blockIdx.x;
    int t = threadIdx.x;
    const float* xr = x + (size_t)n * Dd;
    float a0 = 0.f, a1 = 0.f, a2 = 0.f;
    for (int d = t; d < Dd; d += 128) {
        float xv = xr[d];
        g_xh[(size_t)n * Dd + d] = __float2half(xv);
        a0 += xv * Wr[d];
        a1 += xv * Wr[Dd + d];
        a2 += xv * Wr[2 * Dd + d];
    }
    __shared__ float s0[128], s1[128], s2[128];
    s0[t] = a0; s1[t] = a1; s2[t] = a2;
    __syncthreads();
    for (int off = 64; off > 0; off >>= 1) {
        if (t < off) { s0[t] += s0[t+off]; s1[t] += s1[t+off]; s2[t] += s2[t+off]; }
        __syncthreads();
    }
    if (t == 0) {
        float z0 = s0[0], z1 = s1[0], z2 = s2[0];
        const float inv3 = 0.57735026918962576f;
        float logits[Ee];
        #pragma unroll
        for (int e = 0; e < Ee; e++) {
            float d0 = (e & 4) ? 1.f : -1.f;
            float d1 = (e & 2) ? 1.f : -1.f;
            float d2 = (e & 1) ? 1.f : -1.f;
            logits[e] = (d0 * z0 + d1 * z1 + d2 * z2) * inv3;
        }
        float m = logits[0];
        #pragma unroll
        for (int e = 1; e < Ee; e++) m = fmaxf(m, logits[e]);
        float p[Ee]; float sum = 0.f;
        #pragma unroll
        for (int e = 0; e < Ee; e++) { p[e] = expf(logits[e] - m); sum += p[e]; }
        float invs = 1.f / sum;
        #pragma unroll
        for (int e = 0; e < Ee; e++) atomicAdd(&g_probsum[e], p[e] * invs);
        int i0 = 0;
        #pragma unroll
        for (int e = 1; e < Ee; e++) if (p[e] > p[i0]) i0 = e;
        int i1 = (i0 == 0) ? 1 : 0;
        #pragma unroll
        for (int e = 0; e < Ee; e++) if (e != i0 && p[e] > p[i1]) i1 = e;
        float v0 = p[i0], v1 = p[i1];
        float wd = 1.f / (v0 + v1);
        g_topw[n*2]   = v0 * wd; g_topw[n*2+1] = v1 * wd;
        int pos0 = atomicAdd(&g_counts[i0], 1);
        int pos1 = atomicAdd(&g_counts[i1], 1);
        int slot0 = i0 * CAP + pos0;
        int slot1 = i1 * CAP + pos1;
        g_slot_tok[slot0] = n;  g_tok_slot[n*2]     = slot0;
        g_slot_tok[slot1] = n;  g_tok_slot[n*2 + 1] = slot1;
    }
    // convert this block's share of W1 to fp16 (hidden under DRAM-idle routing)
    long long qbase = (long long)n * 1152;
    #pragma unroll
    for (int q = 0; q < 9; q++)
        conv_quad(W1, g_w1h, qbase + q * 128 + t);
}

// ---------------- fp16 tensor-core GEMMs ------------------------------------
// Block tile (MI*32) x 128, BK=32. 8 warps 2(m)x4(n), warp tile (MI*16)x32.
// g1: MI=4 (128x128, also converts W2 at entry). g2: MI=2 (64x128).
// ldsm addresses precomputed; k-loop unrolled x4 so buf offsets fold to imms.
#define BKT 32
#define B_BY (32*256)             // 8 KB per stage
#define NST 4

template<bool G1, int MI>
__global__ __launch_bounds__(256, 2) void moe_gemm(const __half* __restrict__ Wglob,
                                                   const float* __restrict__ W2src) {
    constexpr int TM   = MI * 32;
    constexpr int A_BY = TM * 64;
    constexpr int KTOT = G1 ? Dd : Hh;
    constexpr int NSTR = G1 ? Hh : Dd;
    constexpr int NT   = KTOT / BKT;
    constexpr int ACH  = TM / 64;

    int t = threadIdx.x;
    if (G1) {
        // convert this CTA's share of W2 (3072 CTAs x 768 quads)
        int bid = blockIdx.x + gridDim.x * (blockIdx.y + gridDim.y * blockIdx.z);
        long long qbase = (long long)bid * 768;
        #pragma unroll
        for (int q = 0; q < 3; q++)
            conv_quad(W2src, g_w2h, qbase + q * 256 + t);
    }

    int e = blockIdx.z;
    int cnt = g_counts[e];
    int m0 = blockIdx.y * TM;
    if (m0 >= cnt) return;
    int n0 = blockIdx.x * 128;
    int base = e * CAP + m0;
    int rows = min(TM, cnt - m0);

    extern __shared__ char sm[];
    uint32_t uA = (uint32_t)__cvta_generic_to_shared(sm);
    uint32_t uB = uA + NST * A_BY;
    int* stok = (int*)(sm + NST * (A_BY + B_BY));

    int wid = t >> 5, lane = t & 31;
    int wm0 = (wid & 1) * (MI * 16), wn0 = (wid >> 1) * 32;
    int gid = lane >> 2, tig = lane & 3;

    int la_r = (lane & 7) + ((lane >> 3) & 1) * 8;
    int la_u = (lane >> 4) & 1;
    int lb_k = ((lane >> 3) & 1) * 8 + (lane & 7);
    int lb_n = ((lane >> 4) & 1) * 8;

    // precomputed ldsm base addresses (buf 0); per-iter offset folds to imm
    uint32_t a_base[MI][2];
    #pragma unroll
    for (int mi = 0; mi < MI; mi++) {
        int r = wm0 + mi * 16 + la_r;
        #pragma unroll
        for (int ks = 0; ks < 2; ks++) {
            int u = 2 * ks + la_u;
            a_base[mi][ks] = uA + r * 64 + ((u ^ ((r >> 1) & 3)) << 4);
        }
    }
    uint32_t b_base[2];
    #pragma unroll
    for (int half = 0; half < 2; half++) {
        int ncol = wn0 + half * 16 + lb_n;
        int u = ncol >> 3;
        b_base[half] = uB + lb_k * 256 + ((u ^ (lb_k & 7)) << 4);
    }

    const __half* Wb = Wglob + (size_t)e * Dd * Hh;
    const __half* Ag = G1 ? g_xh : g_hh;

    if (G1 && t < TM) stok[t] = (t < rows) ? g_slot_tok[base + t] : -1;
    __syncthreads();

    auto issue = [&](int kt) {
        int buf = kt & (NST - 1);
        uint32_t ab = uA + buf * A_BY;
        uint32_t bb = uB + buf * B_BY;
        #pragma unroll
        for (int i = 0; i < ACH; i++) {
            int idx = i * 256 + t;
            int r = idx >> 2, u = idx & 3;
            uint32_t dst = ab + r * 64 + ((u ^ ((r >> 1) & 3)) << 4);
            if (G1) {
                int tok = stok[r];
                cp16(dst, Ag + (size_t)max(tok, 0) * KTOT + kt * BKT + u * 8,
                     (tok >= 0) ? 16 : 0);
            } else {
                cp16(dst, Ag + (size_t)(base + min(r, rows - 1)) * KTOT + kt * BKT + u * 8,
                     (r < rows) ? 16 : 0);
            }
        }
        #pragma unroll
        for (int i = 0; i < 2; i++) {
            int idx = i * 256 + t;
            int k = idx >> 4, u = idx & 15;
            uint32_t dst = bb + k * 256 + ((u ^ (k & 7)) << 4);
            cp16(dst, Wb + (size_t)(kt * BKT + k) * NSTR + n0 + u * 8, 16);
        }
        asm volatile("cp.async.commit_group;" ::: "memory");
    };

    issue(0); issue(1); issue(2);

    float acc[MI][4][4] = {};

    #pragma unroll 4
    for (int j = 0; j < NT; j++) {
        int buf = j & (NST - 1);
        if (j <= NT - 3)      asm volatile("cp.async.wait_group 2;" ::: "memory");
        else if (j == NT - 2) asm volatile("cp.async.wait_group 1;" ::: "memory");
        else                  asm volatile("cp.async.wait_group 0;" ::: "memory");
        __syncthreads();
        if (j + 3 < NT) issue(j + 3);

        uint32_t aoff = buf * A_BY;
        uint32_t boff = buf * B_BY;

        #pragma unroll
        for (int ks = 0; ks < 2; ks++) {
            uint32_t a[MI][4];
            #pragma unroll
            for (int mi = 0; mi < MI; mi++)
                ldsm4(a[mi], a_base[mi][ks] + aoff);
            uint32_t b[2][4];
            #pragma unroll
            for (int half = 0; half < 2; half++)
                ldsm4t(b[half], b_base[half] + boff + ks * 4096);
            #pragma unroll
            for (int mi = 0; mi < MI; mi++)
                #pragma unroll
                for (int ni = 0; ni < 4; ni++)
                    mma_f16(acc[mi][ni], a[mi][0], a[mi][1], a[mi][2], a[mi][3],
                            b[ni >> 1][(ni & 1) * 2], b[ni >> 1][(ni & 1) * 2 + 1]);
        }
    }

    // epilogue
    #pragma unroll
    for (int mi = 0; mi < MI; mi++) {
        int r0 = wm0 + mi * 16 + gid;
        #pragma unroll
        for (int ni = 0; ni < 4; ni++) {
            int c = n0 + wn0 + ni * 8 + tig * 2;
            #pragma unroll
            for (int half = 0; half < 2; half++) {
                int r = r0 + half * 8;
                if (r < rows) {
                    float v0 = acc[mi][ni][half * 2], v1 = acc[mi][ni][half * 2 + 1];
                    if (G1) {
                        *(__half2*)(g_hh + (size_t)(base + r) * Hh + c) =
                            __floats2half2_rn(gelu_exact(v0), gelu_exact(v1));
                    } else {
                        size_t o = (size_t)(base + r) * Dd + c;
                        g_y[o] = v0; g_y[o + 1] = v1;
                    }
                }
            }
        }
    }
}

#define SM1 (NST*(128*64 + B_BY) + 512)
#define SM2 (NST*(64*64  + B_BY) + 512)

// ---------------- combine (+aux, +state reset) --------------------------------
__global__ void combine_kernel(float* __restrict__ out, int out_size) {
    int idx = blockIdx.x * 256 + threadIdx.x;
    if (idx < Nn * (Dd / 4)) {
        int n = idx / (Dd / 4), q = idx - n * (Dd / 4);
        int s0 = g_tok_slot[n*2], s1 = g_tok_slot[n*2 + 1];
        float w0 = g_topw[n*2], w1 = g_topw[n*2 + 1];
        float4 y0 = *(const float4*)(g_y + (size_t)s0 * Dd + q * 4);
        float4 y1 = *(const float4*)(g_y + (size_t)s1 * Dd + q * 4);
        float4 o;
        o.x = w0 * y0.x + w1 * y1.x;
        o.y = w0 * y0.y + w1 * y1.y;
        o.z = w0 * y0.z + w1 * y1.z;
        o.w = w0 * y0.w + w1 * y1.w;
        *(float4*)(out + (size_t)n * Dd + q * 4) = o;
    }
    if (blockIdx.x == 0 && threadIdx.x == 0) {
        int extra = out_size - Nn * Dd;
        if (extra > 0) {
            float aux = 0.f;
            #pragma unroll
            for (int e = 0; e < Ee; e++) {
                float tpe = g_probsum[e] * (1.0f / (float)Nn);
                float dlt = tpe - 1.0f / (float)Ee;
                aux += dlt * dlt;
            }
            aux = 0.01f * aux / (float)Ee;
            for (int i = 0; i < extra; i++) out[Nn * Dd + i] = aux;
        }
        // restore invariant: counts/probsum zero for next execution
        #pragma unroll
        for (int e = 0; e < Ee; e++) { g_counts[e] = 0; g_probsum[e] = 0.f; }
    }
}

// ---------------- launch -----------------------------------------------------
extern "C" void kernel_launch(void* const* d_in, const int* in_sizes, int n_in,
                              void* d_out, int out_size) {
    const float* x  = (const float*)d_in[0];
    const float* Wr = (const float*)d_in[1];
    const float* W1 = (const float*)d_in[2];
    const float* W2 = (const float*)d_in[3];
    float* out = (float*)d_out;

    cudaFuncSetAttribute(moe_gemm<true, 4>,
                         cudaFuncAttributeMaxDynamicSharedMemorySize, SM1);
    cudaFuncSetAttribute(moe_gemm<false, 2>,
                         cudaFuncAttributeMaxDynamicSharedMemorySize, SM2);

    __half* w1h; cudaGetSymbolAddress((void**)&w1h, g_w1h);
    __half* w2h; cudaGetSymbolAddress((void**)&w2h, g_w2h);

    routing_kernel<<<Nn, 128>>>(x, Wr, W1);
    moe_gemm<true, 4><<<dim3(Hh / 128, Nn / 128, Ee), 256, SM1>>>(w1h, W2);
    moe_gemm<false, 2><<<dim3(Dd / 128, Nn / 64, Ee), 256, SM2>>>(w2h, nullptr);
    combine_kernel<<<(Nn * (Dd / 4) + 255) / 256, 256>>>(out, out_size);
}